// round 5
// baseline (speedup 1.0000x reference)
#include <cstdint>
#include <cuda_runtime.h>
#include <cuda_bf16.h>
#include <math.h>

// Shapes (fixed): B=16, T=128, L=64, D=768
#define BB 16
#define TT 128
#define LL 64
#define DD 768
#define TG 4                      // t's per attention block

__device__ float g_kfull[BB * LL * DD];
__device__ float g_ktil [BB * LL * DD];
__device__ float g_vfull[BB * LL * DD];
__device__ float g_c    [BB * LL];

// ---------------------------------------------------------------------------
// NT GEMM (R3 version): C[r,n] = sum_k A[r,k]*W[n,k] + bias[n]
// BM=64, BN=64, BK=16, 128 threads, micro 4x8. grid (12,16,2).
// ---------------------------------------------------------------------------
__global__ void __launch_bounds__(128) proj_nt_kernel(
    const float* __restrict__ A0, const float* __restrict__ W0, const float* __restrict__ b0,
    const float* __restrict__ A1, const float* __restrict__ W1, const float* __restrict__ b1)
{
    const int K = DD, N = DD;
    const float* A    = blockIdx.z ? A1 : A0;
    const float* W    = blockIdx.z ? W1 : W0;
    const float* bias = blockIdx.z ? b1 : b0;
    float* C          = blockIdx.z ? g_vfull : g_kfull;

    __shared__ float As[16][64];
    __shared__ float Bs[16][64];

    const int tid  = threadIdx.x;
    const int row0 = blockIdx.y * 64;
    const int col0 = blockIdx.x * 64;

    const int lr = tid >> 1;            // 0..63
    const int lh = (tid & 1) * 8;       // 0 or 8
    const int tm = (tid & 15) * 4;      // 0..60
    const int tn = (tid >> 4) * 8;      // 0..56

    float acc[4][8];
    #pragma unroll
    for (int i = 0; i < 4; i++)
        #pragma unroll
        for (int j = 0; j < 8; j++) acc[i][j] = 0.f;

    for (int k0 = 0; k0 < K; k0 += 16) {
        float4 a0 = *(const float4*)(A + (size_t)(row0 + lr) * K + k0 + lh);
        float4 a1 = *(const float4*)(A + (size_t)(row0 + lr) * K + k0 + lh + 4);
        float4 w0 = *(const float4*)(W + (size_t)(col0 + lr) * K + k0 + lh);
        float4 w1 = *(const float4*)(W + (size_t)(col0 + lr) * K + k0 + lh + 4);
        __syncthreads();
        As[lh + 0][lr] = a0.x; As[lh + 1][lr] = a0.y; As[lh + 2][lr] = a0.z; As[lh + 3][lr] = a0.w;
        As[lh + 4][lr] = a1.x; As[lh + 5][lr] = a1.y; As[lh + 6][lr] = a1.z; As[lh + 7][lr] = a1.w;
        Bs[lh + 0][lr] = w0.x; Bs[lh + 1][lr] = w0.y; Bs[lh + 2][lr] = w0.z; Bs[lh + 3][lr] = w0.w;
        Bs[lh + 4][lr] = w1.x; Bs[lh + 5][lr] = w1.y; Bs[lh + 6][lr] = w1.z; Bs[lh + 7][lr] = w1.w;
        __syncthreads();

        #pragma unroll
        for (int k = 0; k < 16; k++) {
            float4 x  = *(const float4*)&As[k][tm];
            float4 y0 = *(const float4*)&Bs[k][tn];
            float4 y1 = *(const float4*)&Bs[k][tn + 4];
            float a[4] = {x.x, x.y, x.z, x.w};
            float bcol[8] = {y0.x, y0.y, y0.z, y0.w, y1.x, y1.y, y1.z, y1.w};
            #pragma unroll
            for (int i = 0; i < 4; i++)
                #pragma unroll
                for (int j = 0; j < 8; j++)
                    acc[i][j] += a[i] * bcol[j];
        }
    }

    float4 ba = *(const float4*)(bias + col0 + tn);
    float4 bb = *(const float4*)(bias + col0 + tn + 4);
    #pragma unroll
    for (int i = 0; i < 4; i++) {
        float* crow = C + (size_t)(row0 + tm + i) * N + col0 + tn;
        *(float4*)(crow)     = make_float4(acc[i][0] + ba.x, acc[i][1] + ba.y,
                                           acc[i][2] + ba.z, acc[i][3] + ba.w);
        *(float4*)(crow + 4) = make_float4(acc[i][4] + bb.x, acc[i][5] + bb.y,
                                           acc[i][6] + bb.z, acc[i][7] + bb.w);
    }
}

// ---------------------------------------------------------------------------
// NN GEMM (R3 version): g_ktil[r,d] = sum_i g_kfull[r,i] * Wq[i,d]
// BM=64, BN=32, BK=16, 128 threads, micro 4x4. grid (24,16).
// ---------------------------------------------------------------------------
__global__ void __launch_bounds__(128) ktil_nn_kernel(const float* __restrict__ Wq)
{
    const int K = DD, N = DD;
    const float* A = g_kfull;
    float* C = g_ktil;

    __shared__ float As[16][64];
    __shared__ float Bs[16][32];

    const int tid  = threadIdx.x;
    const int row0 = blockIdx.y * 64;
    const int col0 = blockIdx.x * 32;

    const int lr = tid >> 1;
    const int lh = (tid & 1) * 8;
    const int kr = tid >> 3;            // 0..15
    const int c4 = (tid & 7) * 4;       // 0..28
    const int tm = (tid & 15) * 4;
    const int tn = (tid >> 4) * 4;      // 0..28

    float acc[4][4];
    #pragma unroll
    for (int i = 0; i < 4; i++)
        #pragma unroll
        for (int j = 0; j < 4; j++) acc[i][j] = 0.f;

    for (int k0 = 0; k0 < K; k0 += 16) {
        float4 a0 = *(const float4*)(A  + (size_t)(row0 + lr) * K + k0 + lh);
        float4 a1 = *(const float4*)(A  + (size_t)(row0 + lr) * K + k0 + lh + 4);
        float4 wv = *(const float4*)(Wq + (size_t)(k0 + kr)   * N + col0 + c4);
        __syncthreads();
        As[lh + 0][lr] = a0.x; As[lh + 1][lr] = a0.y; As[lh + 2][lr] = a0.z; As[lh + 3][lr] = a0.w;
        As[lh + 4][lr] = a1.x; As[lh + 5][lr] = a1.y; As[lh + 6][lr] = a1.z; As[lh + 7][lr] = a1.w;
        *(float4*)&Bs[kr][c4] = wv;
        __syncthreads();

        #pragma unroll
        for (int k = 0; k < 16; k++) {
            float4 x = *(const float4*)&As[k][tm];
            float4 y = *(const float4*)&Bs[k][tn];
            float a[4] = {x.x, x.y, x.z, x.w};
            float bcol[4] = {y.x, y.y, y.z, y.w};
            #pragma unroll
            for (int i = 0; i < 4; i++)
                #pragma unroll
                for (int j = 0; j < 4; j++)
                    acc[i][j] += a[i] * bcol[j];
        }
    }

    #pragma unroll
    for (int i = 0; i < 4; i++)
        *(float4*)(C + (size_t)(row0 + tm + i) * N + col0 + tn) =
            make_float4(acc[i][0], acc[i][1], acc[i][2], acc[i][3]);
}

// ---------------------------------------------------------------------------
// g_c[r] = dot(g_kfull[r,:], bq)
// ---------------------------------------------------------------------------
__global__ void __launch_bounds__(256) bias_dot_kernel(const float* __restrict__ bq)
{
    int row  = blockIdx.x * 8 + (threadIdx.x >> 5);
    int lane = threadIdx.x & 31;
    const float* r = g_kfull + (size_t)row * DD;
    float acc = 0.f;
    #pragma unroll
    for (int j = 0; j < DD / 32; j++)
        acc += r[lane + 32 * j] * bq[lane + 32 * j];
    #pragma unroll
    for (int o = 16; o; o >>= 1) acc += __shfl_xor_sync(0xffffffffu, acc, o);
    if (lane == 0) g_c[row] = acc;
}

// ===========================================================================
// Fused attention, barrier-free main loop.
// Block = (t-group of TG=4, b), 256 threads. Thread (tt, l) = (tid>>6, tid&63)
// computes the FULL dot q(b,t0+tt,l,:) . ktil(b,l,:) via direct LDG,
// unrolled 8 x float4 (one 128B line per row per iteration, MLP ~16).
// Then softmax (4 warps) and streaming output (v read once per row).
// ===========================================================================
__global__ void __launch_bounds__(256, 3) attn_kernel(const float* __restrict__ query,
                                                      float* __restrict__ out)
{
    __shared__ float s_sc[TG][LL];
    __shared__ float s_attn[TG][LL];

    const int t0   = blockIdx.x * TG;
    const int b    = blockIdx.y;
    const int tid  = threadIdx.x;
    const int wid  = tid >> 5;
    const int lane = tid & 31;

    const float rs = 0.03608439182435161f;  // 1/sqrt(768)

    // ---- Phase 1: per-thread dot product ----
    {
        const int tt = tid >> 6;             // 0..3
        const int l  = tid & 63;             // 0..63
        const float4* qr = (const float4*)(query +
            ((size_t)(b * TT + t0 + tt) * LL + l) * DD);
        const float4* kr = (const float4*)(g_ktil +
            ((size_t)b * LL + l) * DD);

        float acc = 0.f;
        #pragma unroll 1
        for (int j = 0; j < DD / 4; j += 8) {
            float4 q0 = qr[j + 0], q1 = qr[j + 1], q2 = qr[j + 2], q3 = qr[j + 3];
            float4 q4 = qr[j + 4], q5 = qr[j + 5], q6 = qr[j + 6], q7 = qr[j + 7];
            float4 k0 = kr[j + 0], k1 = kr[j + 1], k2 = kr[j + 2], k3 = kr[j + 3];
            float4 k4 = kr[j + 4], k5 = kr[j + 5], k6 = kr[j + 6], k7 = kr[j + 7];
            acc += q0.x * k0.x + q0.y * k0.y + q0.z * k0.z + q0.w * k0.w;
            acc += q1.x * k1.x + q1.y * k1.y + q1.z * k1.z + q1.w * k1.w;
            acc += q2.x * k2.x + q2.y * k2.y + q2.z * k2.z + q2.w * k2.w;
            acc += q3.x * k3.x + q3.y * k3.y + q3.z * k3.z + q3.w * k3.w;
            acc += q4.x * k4.x + q4.y * k4.y + q4.z * k4.z + q4.w * k4.w;
            acc += q5.x * k5.x + q5.y * k5.y + q5.z * k5.z + q5.w * k5.w;
            acc += q6.x * k6.x + q6.y * k6.y + q6.z * k6.z + q6.w * k6.w;
            acc += q7.x * k7.x + q7.y * k7.y + q7.z * k7.z + q7.w * k7.w;
        }
        s_sc[tt][l] = (acc + g_c[b * LL + l]) * rs;
    }
    __syncthreads();

    // ---- Phase 2: softmax (warps 0..TG-1, one t each) ----
    if (wid < TG) {
        float v0 = s_sc[wid][lane], v1 = s_sc[wid][lane + 32];
        float m = fmaxf(v0, v1);
        #pragma unroll
        for (int o = 16; o; o >>= 1) m = fmaxf(m, __shfl_xor_sync(0xffffffffu, m, o));
        float e0 = expf(v0 - m), e1 = expf(v1 - m);
        float s = e0 + e1;
        #pragma unroll
        for (int o = 16; o; o >>= 1) s += __shfl_xor_sync(0xffffffffu, s, o);
        float inv = 1.f / s;
        s_attn[wid][lane]      = e0 * inv;
        s_attn[wid][lane + 32] = e1 * inv;
    }
    __syncthreads();

    // ---- Phase 3: out(t,l,:) = attn[t][l] * v(b,l,:) ----
    const float4* vb = (const float4*)g_vfull + (size_t)b * LL * 192;
    #pragma unroll 1
    for (int l = wid; l < LL; l += 8) {
        const float4* vr = vb + (size_t)l * 192;
        float4 v0 = vr[lane], v1 = vr[lane + 32], v2 = vr[lane + 64],
               v3 = vr[lane + 96], v4 = vr[lane + 128], v5 = vr[lane + 160];
        #pragma unroll
        for (int tt = 0; tt < TG; tt++) {
            const float a = s_attn[tt][l];
            float4* orow = (float4*)out + ((size_t)(b * TT + t0 + tt) * LL + l) * 192;
            orow[lane]       = make_float4(a * v0.x, a * v0.y, a * v0.z, a * v0.w);
            orow[lane + 32]  = make_float4(a * v1.x, a * v1.y, a * v1.z, a * v1.w);
            orow[lane + 64]  = make_float4(a * v2.x, a * v2.y, a * v2.z, a * v2.w);
            orow[lane + 96]  = make_float4(a * v3.x, a * v3.y, a * v3.z, a * v3.w);
            orow[lane + 128] = make_float4(a * v4.x, a * v4.y, a * v4.z, a * v4.w);
            orow[lane + 160] = make_float4(a * v5.x, a * v5.y, a * v5.z, a * v5.w);
        }
    }
}

// ---------------------------------------------------------------------------
extern "C" void kernel_launch(void* const* d_in, const int* in_sizes, int n_in,
                              void* d_out, int out_size)
{
    const float* query = (const float*)d_in[0];
    const float* key   = (const float*)d_in[1];
    const float* value = (const float*)d_in[2];
    const float* Wq    = (const float*)d_in[3];
    const float* bq    = (const float*)d_in[4];
    const float* Wk    = (const float*)d_in[5];
    const float* bk    = (const float*)d_in[6];
    const float* Wv    = (const float*)d_in[7];
    const float* bv    = (const float*)d_in[8];
    float* out = (float*)d_out;

    proj_nt_kernel<<<dim3(DD / 64, (BB * LL) / 64, 2), 128>>>(key, Wk, bk, value, Wv, bv);
    ktil_nn_kernel<<<dim3(DD / 32, (BB * LL) / 64), 128>>>(Wq);
    bias_dot_kernel<<<(BB * LL) / 8, 256>>>(bq);
    attn_kernel<<<dim3(TT / TG, BB), 256>>>(query, out);
}

// round 6
// speedup vs baseline: 1.4570x; 1.4570x over previous
#include <cstdint>
#include <cuda_runtime.h>
#include <cuda_bf16.h>
#include <mma.h>
#include <math.h>

using namespace nvcuda;

// Shapes (fixed): B=16, T=128, L=64, D=768
#define BB 16
#define TT 128
#define LL 64
#define DD 768
#define TG 4                      // t's per attention block

__device__ float g_kfull[BB * LL * DD];
__device__ float g_ktil [BB * LL * DD];
__device__ float g_vfull[BB * LL * DD];
__device__ float g_c    [BB * LL];

// ---------------------------------------------------------------------------
// Split-bf16 helper: hi = bf16(x), lo = bf16(x - hi).  x ~= hi + lo to ~2^-17.
// ---------------------------------------------------------------------------
__device__ __forceinline__ void cvt8(__nv_bfloat16* hi, __nv_bfloat16* lo,
                                     float4 a, float4 b)
{
    float v[8] = {a.x, a.y, a.z, a.w, b.x, b.y, b.z, b.w};
    #pragma unroll
    for (int i = 0; i < 8; i++) {
        __nv_bfloat16 h = __float2bfloat16(v[i]);
        hi[i] = h;
        lo[i] = __float2bfloat16(v[i] - __bfloat162float(h));
    }
}

// ---------------------------------------------------------------------------
// Tensor-core NT GEMM: C[r,n] = sum_k A[r,k]*W[n,k] + bias[n]
// BM=BN=64, BK=16, 128 threads (4 warps, each 32x32 C).
// Split bf16: c += ah*bh + ah*bl + al*bh   (lo*lo dropped, ~2^-16 rel)
// grid (12, 16, 2): z selects (key,Wk,bk)->g_kfull / (value,Wv,bv)->g_vfull
// ---------------------------------------------------------------------------
__global__ void __launch_bounds__(128) proj_tc_nt(
    const float* __restrict__ A0, const float* __restrict__ W0, const float* __restrict__ b0,
    const float* __restrict__ A1, const float* __restrict__ W1, const float* __restrict__ b1)
{
    const float* A    = blockIdx.z ? A1 : A0;
    const float* W    = blockIdx.z ? W1 : W0;
    const float* bias = blockIdx.z ? b1 : b0;
    float* C          = blockIdx.z ? g_vfull : g_kfull;

    __shared__ __align__(32) __nv_bfloat16 Ahi[64][16], Alo[64][16];
    __shared__ __align__(32) __nv_bfloat16 Bhi[64][16], Blo[64][16];
    __shared__ float biasTile[16][64];

    const int tid  = threadIdx.x;
    const int warp = tid >> 5;
    const int wr   = (warp >> 1) * 32;
    const int wc   = (warp & 1) * 32;
    const int row0 = blockIdx.y * 64;
    const int col0 = blockIdx.x * 64;

    // bias tile: 16 identical rows (accumulator init trick)
    {
        int r = tid >> 3, cb = (tid & 7) * 8;
        #pragma unroll
        for (int i = 0; i < 8; i++) biasTile[r][cb + i] = bias[col0 + cb + i];
    }
    __syncthreads();

    wmma::fragment<wmma::accumulator, 16, 16, 16, float> c[2][2];
    #pragma unroll
    for (int i = 0; i < 2; i++)
        #pragma unroll
        for (int j = 0; j < 2; j++)
            wmma::load_matrix_sync(c[i][j], &biasTile[0][wc + 16 * j], 64,
                                   wmma::mem_row_major);

    const int lr = tid >> 1;          // 0..63
    const int lc = (tid & 1) * 8;     // 0 or 8

    for (int k0 = 0; k0 < DD; k0 += 16) {
        float4 av0 = *(const float4*)(A + (size_t)(row0 + lr) * DD + k0 + lc);
        float4 av1 = *(const float4*)(A + (size_t)(row0 + lr) * DD + k0 + lc + 4);
        float4 wv0 = *(const float4*)(W + (size_t)(col0 + lr) * DD + k0 + lc);
        float4 wv1 = *(const float4*)(W + (size_t)(col0 + lr) * DD + k0 + lc + 4);
        __syncthreads();
        cvt8(&Ahi[lr][lc], &Alo[lr][lc], av0, av1);
        cvt8(&Bhi[lr][lc], &Blo[lr][lc], wv0, wv1);
        __syncthreads();

        wmma::fragment<wmma::matrix_a, 16, 16, 16, __nv_bfloat16, wmma::row_major> ah[2], al[2];
        wmma::fragment<wmma::matrix_b, 16, 16, 16, __nv_bfloat16, wmma::col_major> bh[2], bl[2];
        #pragma unroll
        for (int i = 0; i < 2; i++) {
            wmma::load_matrix_sync(ah[i], &Ahi[wr + 16 * i][0], 16);
            wmma::load_matrix_sync(al[i], &Alo[wr + 16 * i][0], 16);
        }
        #pragma unroll
        for (int j = 0; j < 2; j++) {
            wmma::load_matrix_sync(bh[j], &Bhi[wc + 16 * j][0], 16);
            wmma::load_matrix_sync(bl[j], &Blo[wc + 16 * j][0], 16);
        }
        #pragma unroll
        for (int i = 0; i < 2; i++)
            #pragma unroll
            for (int j = 0; j < 2; j++) {
                wmma::mma_sync(c[i][j], ah[i], bh[j], c[i][j]);
                wmma::mma_sync(c[i][j], ah[i], bl[j], c[i][j]);
                wmma::mma_sync(c[i][j], al[i], bh[j], c[i][j]);
            }
    }

    #pragma unroll
    for (int i = 0; i < 2; i++)
        #pragma unroll
        for (int j = 0; j < 2; j++)
            wmma::store_matrix_sync(
                C + (size_t)(row0 + wr + 16 * i) * DD + col0 + wc + 16 * j,
                c[i][j], DD, wmma::mem_row_major);
}

// ---------------------------------------------------------------------------
// Tensor-core NN GEMM: g_ktil[r,d] = sum_i g_kfull[r,i] * Wq[i,d]
// Same tiling; B is row-major Wq. grid (12, 16).
// ---------------------------------------------------------------------------
__global__ void __launch_bounds__(128) ktil_tc_nn(const float* __restrict__ Wq)
{
    const float* A = g_kfull;
    float* C = g_ktil;

    __shared__ __align__(32) __nv_bfloat16 Ahi[64][16], Alo[64][16];
    __shared__ __align__(32) __nv_bfloat16 Bhi[16][64], Blo[16][64];

    const int tid  = threadIdx.x;
    const int warp = tid >> 5;
    const int wr   = (warp >> 1) * 32;
    const int wc   = (warp & 1) * 32;
    const int row0 = blockIdx.y * 64;
    const int col0 = blockIdx.x * 64;

    wmma::fragment<wmma::accumulator, 16, 16, 16, float> c[2][2];
    #pragma unroll
    for (int i = 0; i < 2; i++)
        #pragma unroll
        for (int j = 0; j < 2; j++)
            wmma::fill_fragment(c[i][j], 0.f);

    const int lr = tid >> 1;          // A loader: 0..63
    const int lc = (tid & 1) * 8;
    const int kr = tid >> 3;          // B loader: 0..15
    const int kc = (tid & 7) * 8;     // 0..56

    for (int k0 = 0; k0 < DD; k0 += 16) {
        float4 av0 = *(const float4*)(A  + (size_t)(row0 + lr) * DD + k0 + lc);
        float4 av1 = *(const float4*)(A  + (size_t)(row0 + lr) * DD + k0 + lc + 4);
        float4 wv0 = *(const float4*)(Wq + (size_t)(k0 + kr) * DD + col0 + kc);
        float4 wv1 = *(const float4*)(Wq + (size_t)(k0 + kr) * DD + col0 + kc + 4);
        __syncthreads();
        cvt8(&Ahi[lr][lc], &Alo[lr][lc], av0, av1);
        cvt8(&Bhi[kr][kc], &Blo[kr][kc], wv0, wv1);
        __syncthreads();

        wmma::fragment<wmma::matrix_a, 16, 16, 16, __nv_bfloat16, wmma::row_major> ah[2], al[2];
        wmma::fragment<wmma::matrix_b, 16, 16, 16, __nv_bfloat16, wmma::row_major> bh[2], bl[2];
        #pragma unroll
        for (int i = 0; i < 2; i++) {
            wmma::load_matrix_sync(ah[i], &Ahi[wr + 16 * i][0], 16);
            wmma::load_matrix_sync(al[i], &Alo[wr + 16 * i][0], 16);
        }
        #pragma unroll
        for (int j = 0; j < 2; j++) {
            wmma::load_matrix_sync(bh[j], &Bhi[0][wc + 16 * j], 64);
            wmma::load_matrix_sync(bl[j], &Blo[0][wc + 16 * j], 64);
        }
        #pragma unroll
        for (int i = 0; i < 2; i++)
            #pragma unroll
            for (int j = 0; j < 2; j++) {
                wmma::mma_sync(c[i][j], ah[i], bh[j], c[i][j]);
                wmma::mma_sync(c[i][j], ah[i], bl[j], c[i][j]);
                wmma::mma_sync(c[i][j], al[i], bh[j], c[i][j]);
            }
    }

    #pragma unroll
    for (int i = 0; i < 2; i++)
        #pragma unroll
        for (int j = 0; j < 2; j++)
            wmma::store_matrix_sync(
                C + (size_t)(row0 + wr + 16 * i) * DD + col0 + wc + 16 * j,
                c[i][j], DD, wmma::mem_row_major);
}

// ---------------------------------------------------------------------------
// g_c[r] = dot(g_kfull[r,:], bq)
// ---------------------------------------------------------------------------
__global__ void __launch_bounds__(256) bias_dot_kernel(const float* __restrict__ bq)
{
    int row  = blockIdx.x * 8 + (threadIdx.x >> 5);
    int lane = threadIdx.x & 31;
    const float* r = g_kfull + (size_t)row * DD;
    float acc = 0.f;
    #pragma unroll
    for (int j = 0; j < DD / 32; j++)
        acc += r[lane + 32 * j] * bq[lane + 32 * j];
    #pragma unroll
    for (int o = 16; o; o >>= 1) acc += __shfl_xor_sync(0xffffffffu, acc, o);
    if (lane == 0) g_c[row] = acc;
}

// ===========================================================================
// Fused attention (R3 layout + k prefetch): block = (t-group of 4, b),
// 256 threads. q staged via cp.async double buffer (2 x 49KB), ktil row for
// the NEXT chunk prefetched via LDG before the cp.async wait.
// ===========================================================================
#define STAGE_FLOATS (TG * 8 * 384)          // 12288 floats = 49152 B
#define STAGE_BYTES  (STAGE_FLOATS * 4)

__device__ __forceinline__ void cp_async16(uint32_t dst, const void* src) {
    asm volatile("cp.async.cg.shared.global [%0], [%1], 16;\n" :: "r"(dst), "l"(src) : "memory");
}

__global__ void __launch_bounds__(256) attn_kernel(const float* __restrict__ query,
                                                   float* __restrict__ out)
{
    extern __shared__ float sq[];            // 2 * STAGE_FLOATS
    __shared__ float s_sc[TG][LL];
    __shared__ float s_attn[TG][LL];

    const int t0   = blockIdx.x * TG;
    const int b    = blockIdx.y;
    const int tid  = threadIdx.x;
    const int wid  = tid >> 5;
    const int lane = tid & 31;

    const float rs = 0.03608439182435161f;  // 1/sqrt(768)

    const uint32_t smq = (uint32_t)__cvta_generic_to_shared(sq);

    // cp.async mapping (per chunk of 8 labels x 384 floats x TG t's)
    const int tt_w  = tid >> 3;
    const int cw_tt = tt_w >> 3;             // which t in group
    const int cw_w  = tt_w & 7;              // label within group of 8
    const int colb  = tid & 7;

    const float4* kb = (const float4*)g_ktil + (size_t)b * LL * (DD / 4);

    float acc[TG];
    #pragma unroll
    for (int tt = 0; tt < TG; tt++) acc[tt] = 0.f;

    // ---- issue chunk 0 (stage 0) ----
    {
        const float* src = query + ((size_t)(b * TT + t0 + cw_tt) * LL + cw_w) * DD;
        uint32_t dst = smq + (uint32_t)(tt_w * 96) * 16;
        #pragma unroll
        for (int j = 0; j < 12; j++) {
            int c4 = colb + 8 * j;
            cp_async16(dst + c4 * 16, src + c4 * 4);
        }
        asm volatile("cp.async.commit_group;\n" ::: "memory");
    }

    // ---- preload k for chunk 0 ----
    float4 k0, k1, k2;
    {
        const float4* krow = kb + (size_t)wid * 192;   // lg=0, h=0, l=wid
        k0 = krow[lane]; k1 = krow[lane + 32]; k2 = krow[lane + 64];
    }

    for (int c = 0; c < 16; c++) {
        float4 n0, n1, n2;
        if (c < 15) {
            const int lg = (c + 1) >> 1, h = (c + 1) & 1;
            // issue next q chunk
            const float* src = query +
                ((size_t)(b * TT + t0 + cw_tt) * LL + (lg * 8 + cw_w)) * DD + h * 384;
            uint32_t dst = smq + (uint32_t)(((c + 1) & 1) * STAGE_BYTES)
                               + (uint32_t)(tt_w * 96) * 16;
            #pragma unroll
            for (int j = 0; j < 12; j++) {
                int c4 = colb + 8 * j;
                cp_async16(dst + c4 * 16, src + c4 * 4);
            }
            asm volatile("cp.async.commit_group;\n" ::: "memory");
            // prefetch next k (overlaps the cp.async wait)
            const float4* krow = kb + (size_t)(lg * 8 + wid) * 192 + h * 96;
            n0 = krow[lane]; n1 = krow[lane + 32]; n2 = krow[lane + 64];
            asm volatile("cp.async.wait_group 1;\n" ::: "memory");
        } else {
            asm volatile("cp.async.wait_group 0;\n" ::: "memory");
        }
        __syncthreads();

        // compute on stage c&1 with the prefetched k regs
        const int lg = c >> 1, h = c & 1;
        const int l = lg * 8 + wid;
        const float4* sqf = (const float4*)(sq + (c & 1) * STAGE_FLOATS);

        #pragma unroll
        for (int tt = 0; tt < TG; tt++) {
            const float4* qs = sqf + (tt * 8 + wid) * 96;
            float4 q0 = qs[lane], q1 = qs[lane + 32], q2 = qs[lane + 64];
            acc[tt] += q0.x * k0.x + q0.y * k0.y + q0.z * k0.z + q0.w * k0.w
                     + q1.x * k1.x + q1.y * k1.y + q1.z * k1.z + q1.w * k1.w
                     + q2.x * k2.x + q2.y * k2.y + q2.z * k2.z + q2.w * k2.w;
        }

        if (h == 1) {
            #pragma unroll
            for (int tt = 0; tt < TG; tt++) {
                float r = acc[tt];
                #pragma unroll
                for (int o = 16; o; o >>= 1) r += __shfl_xor_sync(0xffffffffu, r, o);
                if (lane == 0) s_sc[tt][l] = (r + g_c[b * LL + l]) * rs;
                acc[tt] = 0.f;
            }
        }
        __syncthreads();

        k0 = n0; k1 = n1; k2 = n2;
    }

    // ---- softmax (warps 0..TG-1, one t each) ----
    if (wid < TG) {
        float v0 = s_sc[wid][lane], v1 = s_sc[wid][lane + 32];
        float m = fmaxf(v0, v1);
        #pragma unroll
        for (int o = 16; o; o >>= 1) m = fmaxf(m, __shfl_xor_sync(0xffffffffu, m, o));
        float e0 = expf(v0 - m), e1 = expf(v1 - m);
        float s = e0 + e1;
        #pragma unroll
        for (int o = 16; o; o >>= 1) s += __shfl_xor_sync(0xffffffffu, s, o);
        float inv = 1.f / s;
        s_attn[wid][lane]      = e0 * inv;
        s_attn[wid][lane + 32] = e1 * inv;
    }
    __syncthreads();

    // ---- output: read each v row once, write TG scaled rows ----
    const float4* vb = (const float4*)g_vfull + (size_t)b * LL * 192;
    #pragma unroll 1
    for (int l = wid; l < LL; l += 8) {
        const float4* vr = vb + (size_t)l * 192;
        float4 v0 = vr[lane], v1 = vr[lane + 32], v2 = vr[lane + 64],
               v3 = vr[lane + 96], v4 = vr[lane + 128], v5 = vr[lane + 160];
        #pragma unroll
        for (int tt = 0; tt < TG; tt++) {
            const float a = s_attn[tt][l];
            float4* orow = (float4*)out + ((size_t)(b * TT + t0 + tt) * LL + l) * 192;
            orow[lane]       = make_float4(a * v0.x, a * v0.y, a * v0.z, a * v0.w);
            orow[lane + 32]  = make_float4(a * v1.x, a * v1.y, a * v1.z, a * v1.w);
            orow[lane + 64]  = make_float4(a * v2.x, a * v2.y, a * v2.z, a * v2.w);
            orow[lane + 96]  = make_float4(a * v3.x, a * v3.y, a * v3.z, a * v3.w);
            orow[lane + 128] = make_float4(a * v4.x, a * v4.y, a * v4.z, a * v4.w);
            orow[lane + 160] = make_float4(a * v5.x, a * v5.y, a * v5.z, a * v5.w);
        }
    }
}

// ---------------------------------------------------------------------------
extern "C" void kernel_launch(void* const* d_in, const int* in_sizes, int n_in,
                              void* d_out, int out_size)
{
    const float* query = (const float*)d_in[0];
    const float* key   = (const float*)d_in[1];
    const float* value = (const float*)d_in[2];
    const float* Wq    = (const float*)d_in[3];
    const float* bq    = (const float*)d_in[4];
    const float* Wk    = (const float*)d_in[5];
    const float* bk    = (const float*)d_in[6];
    const float* Wv    = (const float*)d_in[7];
    const float* bv    = (const float*)d_in[8];
    float* out = (float*)d_out;

    static int smem_set = 0;
    if (!smem_set) {
        cudaFuncSetAttribute(attn_kernel, cudaFuncAttributeMaxDynamicSharedMemorySize,
                             2 * STAGE_BYTES);
        smem_set = 1;
    }

    proj_tc_nt<<<dim3(DD / 64, (BB * LL) / 64, 2), 128>>>(key, Wk, bk, value, Wv, bv);
    ktil_tc_nn<<<dim3(DD / 64, (BB * LL) / 64), 128>>>(Wq);
    bias_dot_kernel<<<(BB * LL) / 8, 256>>>(bq);
    attn_kernel<<<dim3(TT / TG, BB), 256, 2 * STAGE_BYTES>>>(query, out);
}